// round 14
// baseline (speedup 1.0000x reference)
#include <cuda_runtime.h>
#include <cuda_fp16.h>
#include <cstdint>

#define FLEN 1024
#define DDIM 1024
#define HALF 512            // steps per direction
#define NGRP 32             // blocks per direction
#define NBLK (2*NGRP)
#define TPB  512
#define TILE_BYTES 65536    // 32 vectors x 1024 halves x 2B
#define SENT 0x7FA00BADu    // qNaN payload; chain data is strictly positive

// dynamic smem layout
#define SMEM_SV    (3*TILE_BYTES)           // float[1024]
#define SMEM_SX    (SMEM_SV + 4096)         // int[512]
#define SMEM_SP    (SMEM_SX + 2048)         // float[512] partials
#define SMEM_MBAR  (SMEM_SP + 2048)
#define SMEM_TOTAL (SMEM_MBAR + 64)

// fp16 copies of core (built each launch; idempotent).
__device__ __align__(128) __half g_ct[(size_t)32*1024*1024]; // column-major
__device__ __align__(128) __half g_cr[(size_t)32*1024*1024]; // row-major

// WRITE-ONCE self-validating chain-vector buffers (no ring reuse, no clears:
// every (step, element) location is written exactly once per launch, so the
// only writes a reader can observe are the launch-start sentinel fill and the
// unique publish — sound under per-location coherence alone).
__device__ __align__(16) float g_bV[HALF][DDIM];
__device__ __align__(16) float g_bW[HALF][DDIM];

// ---------------- helpers ----------------
__device__ __forceinline__ float ld_vol_f32(const float* p) {
    float v;
    asm volatile("ld.volatile.global.f32 %0, [%1];" : "=f"(v) : "l"(p) : "memory");
    return v;
}
__device__ __forceinline__ void st_vol_f32(float* p, float v) {
    asm volatile("st.volatile.global.f32 [%0], %1;" :: "l"(p), "f"(v) : "memory");
}
__device__ __forceinline__ unsigned smem_u32(const void* p) {
    unsigned a;
    asm("{ .reg .u64 t; cvta.to.shared.u64 t, %1; cvt.u32.u64 %0, t; }"
        : "=r"(a) : "l"(p));
    return a;
}
__device__ __forceinline__ void mbar_init(unsigned a, unsigned cnt) {
    asm volatile("mbarrier.init.shared.b64 [%0], %1;" :: "r"(a), "r"(cnt) : "memory");
}
__device__ __forceinline__ void mbar_expect(unsigned a, unsigned tx) {
    asm volatile("mbarrier.arrive.expect_tx.shared.b64 _, [%0], %1;"
                 :: "r"(a), "r"(tx) : "memory");
}
__device__ __forceinline__ void bulk_g2s(unsigned dst, const void* src,
                                         unsigned bytes, unsigned mbar) {
    asm volatile("cp.async.bulk.shared::cluster.global.mbarrier::complete_tx::bytes "
                 "[%0], [%1], %2, [%3];"
                 :: "r"(dst), "l"(src), "r"(bytes), "r"(mbar) : "memory");
}
__device__ __forceinline__ void mbar_wait(unsigned a, unsigned ph) {
    unsigned done;
    asm volatile("{ .reg .pred p; "
                 "mbarrier.try_wait.parity.acquire.cta.shared::cta.b64 p, [%1], %2; "
                 "selp.b32 %0, 1, 0, p; }"
                 : "=r"(done) : "r"(a), "r"(ph) : "memory");
    if (!done) {
        asm volatile("{ .reg .pred P1; "
                     "W%=: mbarrier.try_wait.parity.acquire.cta.shared::cta.b64 P1, [%0], %1, 0x989680; "
                     "@P1 bra D%=; bra W%=; D%=: }"
                     :: "r"(a), "r"(ph) : "memory");
    }
}

// ---------------- init: sentinel-fill both buffers (every launch) ----------------
__global__ void init_kernel() {
    const unsigned tid = blockIdx.x * blockDim.x + threadIdx.x;
    const unsigned n = HALF * DDIM;
    const float s = __uint_as_float(SENT);
    for (unsigned i = tid; i < n; i += gridDim.x * blockDim.x) {
        st_vol_f32(&g_bV[0][0] + i, s);
        st_vol_f32(&g_bW[0][0] + i, s);
    }
}

// ---------------- pre-pass: fp32 -> fp16 in two layouts ----------------
__global__ void __launch_bounds__(256, 2)
convert_kernel(const float* __restrict__ core)
{
    __shared__ float s[64][65];
    const int tile = blockIdx.x;
    const int c  = tile >> 8;
    const int i0 = ((tile >> 4) & 15) << 6;
    const int j0 = (tile & 15) << 6;
    const int tid = threadIdx.x;
    const float* src = core + ((size_t)c << 20);

    #pragma unroll
    for (int p = 0; p < 4; ++p) {
        const int fid = tid + (p << 8);
        const int row = fid >> 4, col4 = fid & 15;
        const float4 v = *reinterpret_cast<const float4*>(
            src + ((size_t)(i0 + row) << 10) + j0 + (col4 << 2));
        __half2 h0 = __floats2half2_rn(v.x, v.y);
        __half2 h1 = __floats2half2_rn(v.z, v.w);
        uint2 u = make_uint2(*reinterpret_cast<unsigned*>(&h0),
                             *reinterpret_cast<unsigned*>(&h1));
        *reinterpret_cast<uint2*>(
            &g_cr[(((size_t)c << 10) + (i0 + row)) * 1024 + j0 + (col4 << 2)]) = u;
        s[row][(col4 << 2) + 0] = v.x; s[row][(col4 << 2) + 1] = v.y;
        s[row][(col4 << 2) + 2] = v.z; s[row][(col4 << 2) + 3] = v.w;
    }
    __syncthreads();
    #pragma unroll
    for (int p = 0; p < 4; ++p) {
        const int id = tid + (p << 8);
        const int jr = id >> 4, i4 = id & 15;
        __half2 h0 = __floats2half2_rn(s[(i4 << 2) + 0][jr], s[(i4 << 2) + 1][jr]);
        __half2 h1 = __floats2half2_rn(s[(i4 << 2) + 2][jr], s[(i4 << 2) + 3][jr]);
        uint2 u = make_uint2(*reinterpret_cast<unsigned*>(&h0),
                             *reinterpret_cast<unsigned*>(&h1));
        *reinterpret_cast<uint2*>(
            &g_ct[(((size_t)c << 10) + (j0 + jr)) * 1024 + i0 + (i4 << 2)]) = u;
    }
}

// ---------------- persistent chain kernel (R11 skeleton, write-once buffers) ----------------
__global__ void __launch_bounds__(TPB, 1)
tn_writeonce_kernel(const int*   __restrict__ x,
                    const float* __restrict__ lb,
                    const float* __restrict__ rb,
                    float*       __restrict__ out)
{
    extern __shared__ char smem[];
    float* sv    = reinterpret_cast<float*>(smem + SMEM_SV);
    int*   sx    = reinterpret_cast<int*>  (smem + SMEM_SX);
    float* spart = reinterpret_cast<float*>(smem + SMEM_SP);
    const unsigned sbase = smem_u32(smem);
    const unsigned mb0   = sbase + SMEM_MBAR;

    const int tid = threadIdx.x;
    const int b   = blockIdx.x;
    const int l   = tid & 31;
    const int w   = tid >> 5;      // 16 warps
    const int g   = l >> 3;        // column group 0..3
    const int r   = l & 7;         // i-subrange within warp segment
    const bool fwd = (b < NGRP);
    const int  ob  = fwd ? b : b - NGRP;

    const __half* mat = fwd ? g_ct : g_cr;
    float (*buf)[DDIM] = fwd ? g_bV : g_bW;
    const float* bound = fwd ? lb : rb;

    if (tid == 0) {
        mbar_init(mb0, 1); mbar_init(mb0 + 8, 1); mbar_init(mb0 + 16, 1);
        asm volatile("fence.proxy.async.shared::cta;" ::: "memory");
    }
    if (fwd) { for (int t = tid; t < HALF; t += TPB) sx[t] = x[t]; }
    else     { for (int t = tid; t < HALF; t += TPB) sx[t] = x[FLEN - 1 - t]; }
    __syncthreads();

    const size_t stripe = (size_t)ob << 15;   // 32*1024 halves per block
    if (tid == 0) {   // prime tiles for steps 0 and 1
        mbar_expect(mb0, TILE_BYTES);
        bulk_g2s(sbase, mat + (((size_t)sx[0]) << 20) + stripe, TILE_BYTES, mb0);
        mbar_expect(mb0 + 8, TILE_BYTES);
        bulk_g2s(sbase + TILE_BYTES, mat + (((size_t)sx[1]) << 20) + stripe,
                 TILE_BYTES, mb0 + 8);
    }

    for (int t = 0; t < HALF; ++t) {
        // 1. this step's tile must be resident (TMA issued >= 2 steps ago)
        const int slot = t % 3;
        mbar_wait(mb0 + slot * 8, (unsigned)((t / 3) & 1));

        // 2. load matrix quads into regs (fp16; converted post-poll, as in R11)
        const char* tile = smem + slot * TILE_BYTES;
        uint4 m[8];
        #pragma unroll
        for (int k = 0; k < 8; ++k) {
            const int c = (k << 2) + g;              // vector index 0..31
            m[k] = *reinterpret_cast<const uint4*>(
                tile + c * 2048 + ((w << 3) + r) * 16);
        }

        // 3. queue TMA for step t+2 (slot (t+2)%3 consumed at step t-1)
        if (tid == 0 && t + 2 < HALF) {
            const int s2 = (t + 2) % 3;
            mbar_expect(mb0 + s2 * 8, TILE_BYTES);
            bulk_g2s(sbase + s2 * TILE_BYTES,
                     mat + (((size_t)sx[t + 2]) << 20) + stripe, TILE_BYTES,
                     mb0 + s2 * 8);
        }

        // 4. obtain chain vector: each thread polls TWO write-once 4B records
        float2 myv;
        if (t == 0) {
            myv = reinterpret_cast<const float2*>(bound)[tid];
        } else {
            const float* src = &buf[t - 1][tid << 1];
            do { myv.x = ld_vol_f32(src); }
            while (__float_as_uint(myv.x) == SENT);
            do { myv.y = ld_vol_f32(src + 1); }
            while (__float_as_uint(myv.y) == SENT);
        }
        reinterpret_cast<float2*>(sv)[tid] = myv;
        __syncthreads();

        // 5. compute: warp w covers terms i in [64w, 64w+64) of ALL 32 vectors
        const float4* sf4 = reinterpret_cast<const float4*>(sv);
        const float4 va = sf4[(w << 4) + (r << 1)];
        const float4 vb = sf4[(w << 4) + (r << 1) + 1];
        float acc[8];
        #pragma unroll
        for (int k = 0; k < 8; ++k) {
            float2 f; float s = 0.f;
            f = __half22float2(*reinterpret_cast<const __half2*>(&m[k].x));
            s = fmaf(f.x, va.x, s); s = fmaf(f.y, va.y, s);
            f = __half22float2(*reinterpret_cast<const __half2*>(&m[k].y));
            s = fmaf(f.x, va.z, s); s = fmaf(f.y, va.w, s);
            f = __half22float2(*reinterpret_cast<const __half2*>(&m[k].z));
            s = fmaf(f.x, vb.x, s); s = fmaf(f.y, vb.y, s);
            f = __half22float2(*reinterpret_cast<const __half2*>(&m[k].w));
            s = fmaf(f.x, vb.z, s); s = fmaf(f.y, vb.w, s);
            acc[k] = s;
        }
        #pragma unroll
        for (int k = 0; k < 8; ++k) {
            #pragma unroll
            for (int off = 1; off < 8; off <<= 1)
                acc[k] += __shfl_xor_sync(0xffffffffu, acc[k], off);
        }
        if (r == 0) {
            #pragma unroll
            for (int k = 0; k < 8; ++k) spart[(w << 5) + (k << 2) + g] = acc[k];
        }
        __syncthreads();

        // 6. warp 0: cross-warp reduce (R11 sequential order) + publish 32
        //    write-once scalar records. No clears — nothing to order.
        if (tid < 32) {
            float s = 0.f;
            #pragma unroll
            for (int w2 = 0; w2 < 16; ++w2) s += spart[(w2 << 5) + tid];
            st_vol_f32(&buf[t][(ob << 5) + tid], s);
        }
    }

    // ---- final combine: block 0 polls both final vectors, dots them ----
    if (b == 0) {
        const float* pv = &g_bV[HALF - 1][tid << 1];
        const float* pw = &g_bW[HALF - 1][tid << 1];
        float2 vf, wf;
        do { vf.x = ld_vol_f32(pv);     } while (__float_as_uint(vf.x) == SENT);
        do { vf.y = ld_vol_f32(pv + 1); } while (__float_as_uint(vf.y) == SENT);
        do { wf.x = ld_vol_f32(pw);     } while (__float_as_uint(wf.x) == SENT);
        do { wf.y = ld_vol_f32(pw + 1); } while (__float_as_uint(wf.y) == SENT);
        float part = vf.x * wf.x + vf.y * wf.y;
        #pragma unroll
        for (int off = 16; off > 0; off >>= 1)
            part += __shfl_xor_sync(0xffffffffu, part, off);
        if (l == 0) spart[w] = part;
        __syncthreads();
        if (tid == 0) {
            float s = 0.f;
            #pragma unroll
            for (int w2 = 0; w2 < 16; ++w2) s += spart[w2];
            out[0] = s;
        }
    }
}

extern "C" void kernel_launch(void* const* d_in, const int* in_sizes, int n_in,
                              void* d_out, int out_size) {
    const int*   x    = (const int*)  d_in[0];  // int32[1024]
    const float* core = (const float*)d_in[1];  // f32[32,1024,1024]
    const float* lb   = (const float*)d_in[2];  // f32[1024]
    const float* rb   = (const float*)d_in[3];  // f32[1024]
    float*       out  = (float*)d_out;

    cudaFuncSetAttribute(tn_writeonce_kernel,
                         cudaFuncAttributeMaxDynamicSharedMemorySize, SMEM_TOTAL);
    init_kernel<<<128, 512>>>();
    convert_kernel<<<32 * 16 * 16, 256>>>(core);
    tn_writeonce_kernel<<<NBLK, TPB, SMEM_TOTAL>>>(x, lb, rb, out);
}

// round 15
// speedup vs baseline: 1.0353x; 1.0353x over previous
#include <cuda_runtime.h>
#include <cuda_fp16.h>
#include <cstdint>

#define FLEN 1024
#define DDIM 1024
#define HALF 512            // steps per direction
#define NGRP 32             // blocks per direction
#define NBLK (2*NGRP)
#define TPB  512
#define TILE_BYTES 65536    // 32 vectors x 1024 halves x 2B
#define SENT 0x7FA00BADu    // qNaN payload; chain data is strictly positive

// dynamic smem layout (no sv staging buffer)
#define SMEM_SX    (3*TILE_BYTES)           // int[512]
#define SMEM_SP    (SMEM_SX + 2048)         // float[2][512] partials (dbl buf)
#define SMEM_MBAR  (SMEM_SP + 4096)
#define SMEM_TOTAL (SMEM_MBAR + 64)

// fp16 copies of core (built each launch; idempotent).
__device__ __align__(128) __half g_ct[(size_t)32*1024*1024]; // column-major
__device__ __align__(128) __half g_cr[(size_t)32*1024*1024]; // row-major

// WRITE-ONCE self-validating chain-vector buffers (R14-proven): every
// (step, element) location is written exactly once per launch; readers rely
// only on per-location coherence of naturally-aligned 4B accesses.
__device__ __align__(16) float g_bV[HALF][DDIM];
__device__ __align__(16) float g_bW[HALF][DDIM];

// ---------------- helpers ----------------
__device__ __forceinline__ float ld_vol_f32(const float* p) {
    float v;
    asm volatile("ld.volatile.global.f32 %0, [%1];" : "=f"(v) : "l"(p) : "memory");
    return v;
}
__device__ __forceinline__ void st_vol_f32(float* p, float v) {
    asm volatile("st.volatile.global.f32 [%0], %1;" :: "l"(p), "f"(v) : "memory");
}
__device__ __forceinline__ unsigned smem_u32(const void* p) {
    unsigned a;
    asm("{ .reg .u64 t; cvta.to.shared.u64 t, %1; cvt.u32.u64 %0, t; }"
        : "=r"(a) : "l"(p));
    return a;
}
__device__ __forceinline__ void mbar_init(unsigned a, unsigned cnt) {
    asm volatile("mbarrier.init.shared.b64 [%0], %1;" :: "r"(a), "r"(cnt) : "memory");
}
__device__ __forceinline__ void mbar_expect(unsigned a, unsigned tx) {
    asm volatile("mbarrier.arrive.expect_tx.shared.b64 _, [%0], %1;"
                 :: "r"(a), "r"(tx) : "memory");
}
__device__ __forceinline__ void bulk_g2s(unsigned dst, const void* src,
                                         unsigned bytes, unsigned mbar) {
    asm volatile("cp.async.bulk.shared::cluster.global.mbarrier::complete_tx::bytes "
                 "[%0], [%1], %2, [%3];"
                 :: "r"(dst), "l"(src), "r"(bytes), "r"(mbar) : "memory");
}
__device__ __forceinline__ void mbar_wait(unsigned a, unsigned ph) {
    unsigned done;
    asm volatile("{ .reg .pred p; "
                 "mbarrier.try_wait.parity.acquire.cta.shared::cta.b64 p, [%1], %2; "
                 "selp.b32 %0, 1, 0, p; }"
                 : "=r"(done) : "r"(a), "r"(ph) : "memory");
    if (!done) {
        asm volatile("{ .reg .pred P1; "
                     "W%=: mbarrier.try_wait.parity.acquire.cta.shared::cta.b64 P1, [%0], %1, 0x989680; "
                     "@P1 bra D%=; bra W%=; D%=: }"
                     :: "r"(a), "r"(ph) : "memory");
    }
}

// ---------------- init: sentinel-fill both buffers (every launch) ----------------
__global__ void init_kernel() {
    const unsigned tid = blockIdx.x * blockDim.x + threadIdx.x;
    const unsigned n = HALF * DDIM;
    const float s = __uint_as_float(SENT);
    for (unsigned i = tid; i < n; i += gridDim.x * blockDim.x) {
        st_vol_f32(&g_bV[0][0] + i, s);
        st_vol_f32(&g_bW[0][0] + i, s);
    }
}

// ---------------- pre-pass: fp32 -> fp16 in two layouts ----------------
__global__ void __launch_bounds__(256, 2)
convert_kernel(const float* __restrict__ core)
{
    __shared__ float s[64][65];
    const int tile = blockIdx.x;
    const int c  = tile >> 8;
    const int i0 = ((tile >> 4) & 15) << 6;
    const int j0 = (tile & 15) << 6;
    const int tid = threadIdx.x;
    const float* src = core + ((size_t)c << 20);

    #pragma unroll
    for (int p = 0; p < 4; ++p) {
        const int fid = tid + (p << 8);
        const int row = fid >> 4, col4 = fid & 15;
        const float4 v = *reinterpret_cast<const float4*>(
            src + ((size_t)(i0 + row) << 10) + j0 + (col4 << 2));
        __half2 h0 = __floats2half2_rn(v.x, v.y);
        __half2 h1 = __floats2half2_rn(v.z, v.w);
        uint2 u = make_uint2(*reinterpret_cast<unsigned*>(&h0),
                             *reinterpret_cast<unsigned*>(&h1));
        *reinterpret_cast<uint2*>(
            &g_cr[(((size_t)c << 10) + (i0 + row)) * 1024 + j0 + (col4 << 2)]) = u;
        s[row][(col4 << 2) + 0] = v.x; s[row][(col4 << 2) + 1] = v.y;
        s[row][(col4 << 2) + 2] = v.z; s[row][(col4 << 2) + 3] = v.w;
    }
    __syncthreads();
    #pragma unroll
    for (int p = 0; p < 4; ++p) {
        const int id = tid + (p << 8);
        const int jr = id >> 4, i4 = id & 15;
        __half2 h0 = __floats2half2_rn(s[(i4 << 2) + 0][jr], s[(i4 << 2) + 1][jr]);
        __half2 h1 = __floats2half2_rn(s[(i4 << 2) + 2][jr], s[(i4 << 2) + 3][jr]);
        uint2 u = make_uint2(*reinterpret_cast<unsigned*>(&h0),
                             *reinterpret_cast<unsigned*>(&h1));
        *reinterpret_cast<uint2*>(
            &g_ct[(((size_t)c << 10) + (j0 + jr)) * 1024 + i0 + (i4 << 2)]) = u;
    }
}

// ---------------- persistent chain kernel (write-once + warp dataflow) ----------------
__global__ void __launch_bounds__(TPB, 1)
tn_warponce_kernel(const int*   __restrict__ x,
                   const float* __restrict__ lb,
                   const float* __restrict__ rb,
                   float*       __restrict__ out)
{
    extern __shared__ char smem[];
    int*   sx    = reinterpret_cast<int*>  (smem + SMEM_SX);
    float* spart = reinterpret_cast<float*>(smem + SMEM_SP);  // [2][512]
    const unsigned sbase = smem_u32(smem);
    const unsigned mb0   = sbase + SMEM_MBAR;

    const int tid = threadIdx.x;
    const int b   = blockIdx.x;
    const int l   = tid & 31;
    const int w   = tid >> 5;      // 16 warps
    const int g   = l >> 3;        // column group 0..3
    const int r   = l & 7;         // i-subrange within warp segment
    const int fourR = r << 2;
    const bool fwd = (b < NGRP);
    const int  ob  = fwd ? b : b - NGRP;

    const __half* mat = fwd ? g_ct : g_cr;
    float (*buf)[DDIM] = fwd ? g_bV : g_bW;
    const float* bound = fwd ? lb : rb;

    if (tid == 0) {
        mbar_init(mb0, 1); mbar_init(mb0 + 8, 1); mbar_init(mb0 + 16, 1);
        asm volatile("fence.proxy.async.shared::cta;" ::: "memory");
    }
    if (fwd) { for (int t = tid; t < HALF; t += TPB) sx[t] = x[t]; }
    else     { for (int t = tid; t < HALF; t += TPB) sx[t] = x[FLEN - 1 - t]; }
    __syncthreads();

    const size_t stripe = (size_t)ob << 15;   // 32*1024 halves per block
    if (tid == 0) {   // prime tiles for steps 0 and 1
        mbar_expect(mb0, TILE_BYTES);
        bulk_g2s(sbase, mat + (((size_t)sx[0]) << 20) + stripe, TILE_BYTES, mb0);
        mbar_expect(mb0 + 8, TILE_BYTES);
        bulk_g2s(sbase + TILE_BYTES, mat + (((size_t)sx[1]) << 20) + stripe,
                 TILE_BYTES, mb0 + 8);
    }

    for (int t = 0; t < HALF; ++t) {
        // 1. this step's tile must be resident (TMA issued >= 2 steps ago)
        const int slot = t % 3;
        mbar_wait(mb0 + slot * 8, (unsigned)((t / 3) & 1));

        // 2. load matrix quads AND convert to fp32 registers BEFORE the poll
        //    (cvt latency hides under the inter-block wait)
        const char* tile = smem + slot * TILE_BYTES;
        float4 ma[8], mbq[8];   // quad k: elements i = 64w+8r..+7 of vector 4k+g
        #pragma unroll
        for (int k = 0; k < 8; ++k) {
            const int c = (k << 2) + g;
            const uint4 q = *reinterpret_cast<const uint4*>(
                tile + c * 2048 + ((w << 3) + r) * 16);
            float2 f;
            f = __half22float2(*reinterpret_cast<const __half2*>(&q.x));
            ma[k].x = f.x; ma[k].y = f.y;
            f = __half22float2(*reinterpret_cast<const __half2*>(&q.y));
            ma[k].z = f.x; ma[k].w = f.y;
            f = __half22float2(*reinterpret_cast<const __half2*>(&q.z));
            mbq[k].x = f.x; mbq[k].y = f.y;
            f = __half22float2(*reinterpret_cast<const __half2*>(&q.w));
            mbq[k].z = f.x; mbq[k].w = f.y;
        }

        // 3. queue TMA for step t+2. Slot (t+2)%3 == (t-1)%3: all warps
        //    finished their reg-loads from it during step t-1, before step
        //    t-1's __syncthreads, which tid0 has also passed.
        if (tid == 0 && t + 2 < HALF) {
            const int s2 = (t + 2) % 3;
            mbar_expect(mb0 + s2 * 8, TILE_BYTES);
            bulk_g2s(sbase + s2 * TILE_BYTES,
                     mat + (((size_t)sx[t + 2]) << 20) + stripe, TILE_BYTES,
                     mb0 + s2 * 8);
        }

        // 4. each lane polls ITS OWN 2 write-once records (this warp is gated
        //    by exactly 2 producer blocks); shfl gather replaces smem staging
        float2 myv;
        if (t == 0) {
            myv = *reinterpret_cast<const float2*>(bound + (tid << 1));
        } else {
            const float* src = &buf[t - 1][tid << 1];
            do { myv.x = ld_vol_f32(src); }
            while (__float_as_uint(myv.x) == SENT);
            do { myv.y = ld_vol_f32(src + 1); }
            while (__float_as_uint(myv.y) == SENT);
        }
        float4 va, vb;
        va.x = __shfl_sync(0xffffffffu, myv.x, fourR);
        va.y = __shfl_sync(0xffffffffu, myv.y, fourR);
        va.z = __shfl_sync(0xffffffffu, myv.x, fourR + 1);
        va.w = __shfl_sync(0xffffffffu, myv.y, fourR + 1);
        vb.x = __shfl_sync(0xffffffffu, myv.x, fourR + 2);
        vb.y = __shfl_sync(0xffffffffu, myv.y, fourR + 2);
        vb.z = __shfl_sync(0xffffffffu, myv.x, fourR + 3);
        vb.w = __shfl_sync(0xffffffffu, myv.y, fourR + 3);

        // 5. 64 FMAs + shfl reduce over r (lane bits 0..2); same value order
        //    as R14 (cvt earlier, arithmetic identical)
        float acc[8];
        #pragma unroll
        for (int k = 0; k < 8; ++k) {
            float s = 0.f;
            s = fmaf(ma[k].x, va.x, s);  s = fmaf(ma[k].y, va.y, s);
            s = fmaf(ma[k].z, va.z, s);  s = fmaf(ma[k].w, va.w, s);
            s = fmaf(mbq[k].x, vb.x, s); s = fmaf(mbq[k].y, vb.y, s);
            s = fmaf(mbq[k].z, vb.z, s); s = fmaf(mbq[k].w, vb.w, s);
            acc[k] = s;
        }
        #pragma unroll
        for (int k = 0; k < 8; ++k) {
            #pragma unroll
            for (int off = 1; off < 8; off <<= 1)
                acc[k] += __shfl_xor_sync(0xffffffffu, acc[k], off);
        }
        float* sp = spart + ((t & 1) << 9);    // double-buffered partials
        if (r == 0) {
            #pragma unroll
            for (int k = 0; k < 8; ++k) sp[(w << 5) + (k << 2) + g] = acc[k];
        }
        __syncthreads();   // the ONLY block-wide sync per step

        // 6. warp 0: cross-warp reduce (R14 sequential order) + publish 32
        //    write-once scalar records; other warps run ahead into step t+1
        if (tid < 32) {
            float s = 0.f;
            #pragma unroll
            for (int w2 = 0; w2 < 16; ++w2) s += sp[(w2 << 5) + tid];
            st_vol_f32(&buf[t][(ob << 5) + tid], s);
        }
    }

    // ---- final combine: block 0 polls both final vectors, dots them ----
    if (b == 0) {
        const float* pv = &g_bV[HALF - 1][tid << 1];
        const float* pw = &g_bW[HALF - 1][tid << 1];
        float2 vf, wf;
        do { vf.x = ld_vol_f32(pv);     } while (__float_as_uint(vf.x) == SENT);
        do { vf.y = ld_vol_f32(pv + 1); } while (__float_as_uint(vf.y) == SENT);
        do { wf.x = ld_vol_f32(pw);     } while (__float_as_uint(wf.x) == SENT);
        do { wf.y = ld_vol_f32(pw + 1); } while (__float_as_uint(wf.y) == SENT);
        float part = vf.x * wf.x + vf.y * wf.y;
        #pragma unroll
        for (int off = 16; off > 0; off >>= 1)
            part += __shfl_xor_sync(0xffffffffu, part, off);
        __syncthreads();              // spart buffers fully consumed
        if (l == 0) spart[w] = part;
        __syncthreads();
        if (tid == 0) {
            float s = 0.f;
            #pragma unroll
            for (int w2 = 0; w2 < 16; ++w2) s += spart[w2];
            out[0] = s;
        }
    }
}

extern "C" void kernel_launch(void* const* d_in, const int* in_sizes, int n_in,
                              void* d_out, int out_size) {
    const int*   x    = (const int*)  d_in[0];  // int32[1024]
    const float* core = (const float*)d_in[1];  // f32[32,1024,1024]
    const float* lb   = (const float*)d_in[2];  // f32[1024]
    const float* rb   = (const float*)d_in[3];  // f32[1024]
    float*       out  = (float*)d_out;

    cudaFuncSetAttribute(tn_warponce_kernel,
                         cudaFuncAttributeMaxDynamicSharedMemorySize, SMEM_TOTAL);
    init_kernel<<<128, 512>>>();
    convert_kernel<<<32 * 16 * 16, 256>>>(core);
    tn_warponce_kernel<<<NBLK, TPB, SMEM_TOTAL>>>(x, lb, rb, out);
}